// round 17
// baseline (speedup 1.0000x reference)
#include <cuda_runtime.h>
#include <cstdint>
#include <math.h>

// ---------------- problem constants ----------------
static constexpr int BATCH  = 64;
static constexpr int NA     = 8192;                  // i dimension (mask rows, GEMM M-strip)
static constexpr int NB     = 8192;                  // j dimension (mask cols, GEMM K)
static constexpr int NIT    = 64;                    // i tiles of 128
static constexpr int NJC    = 64;                    // j chunks of 128
static constexpr int NCHUNK = NIT * NJC;             // 4096
static constexpr int NCTA   = 148;                   // persistent grid = #SMs
static constexpr int NTHREADS = 256;                 // 8 warps = 2/SMSP

// s8 tiles, pitch 144 B (9 x 16B): ldmatrix rows + consumer LDS conflict-free (R4-validated)
static constexpr int PITCH    = 144;
static constexpr int TILE_SZ  = 128 * PITCH;         // 18432
static constexpr int STAGE    = 2 * TILE_SZ;         // A(mask) + B(trig) = 36864
static constexpr int ACC_OFF  = 2 * STAGE;           // 73728
static constexpr int SMEM_BYTES = ACC_OFF + 1024;    // 74752
static constexpr int CA_PITCH = 132;                 // floats (2*64*132*4 = 67584 <= 2*STAGE)

// ---------------- device scratch ----------------
__device__ int8_t g_B8[128 * NB];      // rows 0..63 = q127(cos b), 64..127 = q127(sin b); j-major
__device__ float  g_caf[BATCH * NA];   // cos(a)
__device__ float  g_saf[BATCH * NA];   // sin(a)
__device__ float  g_real[BATCH];
__device__ float  g_imag[BATCH];
__device__ unsigned int g_npairs;

// ---------------- helpers ----------------
__device__ __forceinline__ uint32_t smem_u32(const void* p) {
    uint32_t a;
    asm("{ .reg .u64 t; cvta.to.shared.u64 t, %1; cvt.u32.u64 %0, t; }" : "=r"(a) : "l"(p));
    return a;
}
__device__ __forceinline__ void cp_async16(uint32_t s, const void* g) {
    asm volatile("cp.async.cg.shared.global [%0], [%1], 16;" :: "r"(s), "l"(g) : "memory");
}
#define CP_COMMIT()  asm volatile("cp.async.commit_group;" ::: "memory")
#define CP_WAIT0()   asm volatile("cp.async.wait_group 0;" ::: "memory")

#define LDSM_X4(r, addr) \
    asm volatile("ldmatrix.sync.aligned.m8n8.x4.shared.b16 {%0,%1,%2,%3}, [%4];" \
        : "=r"((r)[0]), "=r"((r)[1]), "=r"((r)[2]), "=r"((r)[3]) : "r"(addr))

__device__ __forceinline__ void mma_s8(int* d, const uint32_t* a, uint32_t b0, uint32_t b1) {
    asm volatile(
        "mma.sync.aligned.m16n8k32.row.col.s32.s8.s8.s32 "
        "{%0,%1,%2,%3}, {%4,%5,%6,%7}, {%8,%9}, {%0,%1,%2,%3};"
        : "+r"(d[0]), "+r"(d[1]), "+r"(d[2]), "+r"(d[3])
        : "r"(a[0]), "r"(a[1]), "r"(a[2]), "r"(a[3]), "r"(b0), "r"(b1));
}
__device__ __forceinline__ uint32_t pack01(const uint4 v) {  // int32{0,1}x4 -> 4 s8 bytes (exact)
    return v.x | (v.y << 8) | (v.z << 16) | (v.w << 24);
}

// ---------------- prep: f32 cos/sin(a); s8 q127 trig table for B ----------------
__global__ void plv_prep(const float* __restrict__ pa, const float* __restrict__ pb) {
    int idx = blockIdx.x * blockDim.x + threadIdx.x;
    if (idx < BATCH * NA) {
        float s, c;
        __sincosf(pa[idx], &s, &c);
        g_caf[idx] = c;
        g_saf[idx] = s;
        int b = idx >> 13;
        int j = idx & (NB - 1);
        __sincosf(pb[idx], &s, &c);
        g_B8[(size_t)b * NB + j]        = (int8_t)__float2int_rn(127.0f * c);
        g_B8[(size_t)(b + 64) * NB + j] = (int8_t)__float2int_rn(127.0f * s);
    }
    if (blockIdx.x == 0) {
        if (threadIdx.x < BATCH) { g_real[threadIdx.x] = 0.0f; g_imag[threadIdx.x] = 0.0f; }
        if (threadIdx.x == BATCH) g_npairs = 0u;
    }
}

// ---------------- main: persistent s8 k32 GEMM, X = M @ Btrig ----------------
__global__ void __launch_bounds__(NTHREADS, 1) plv_main(const int* __restrict__ mask) {
    extern __shared__ char smem_raw[];
    const uint32_t sb = smem_u32(smem_raw);

    const int tid  = threadIdx.x;
    const int wid  = tid >> 5;          // 8 warps: 16 i-rows each
    const int lane = tid & 31;
    const int tc   = (lane & 3) * 2;

    const int g0 = (int)(((long long)blockIdx.x * NCHUNK) / NCTA);
    const int g1 = (int)(((long long)(blockIdx.x + 1) * NCHUNK) / NCTA);

    int acc[16][4];                     // nj 0..7 = cos cols, 8..15 = sin cols
#pragma unroll
    for (int nj = 0; nj < 16; ++nj)
#pragma unroll
        for (int r = 0; r < 4; ++r) acc[nj][r] = 0;

    unsigned int msum = 0;

    // ---- A (mask) loader: 16 x LDG.128, coalesced [i][j] (R11-exact shape) ----
    uint4 areg[16];
    auto load_A = [&](int g) {
        const int i0 = (g >> 6) * 128;
        const int j0 = (g & 63) * 128;
        const int* base = mask + (size_t)i0 * NB + j0;
#pragma unroll
        for (int it = 0; it < 16; ++it) {
            const int idx = tid + it * 256;
            const int i = idx >> 5;
            const int j = (idx & 31) * 4;
            areg[it] = *reinterpret_cast<const uint4*>(base + (size_t)i * NB + j);
        }
    };

    // ---- A convert + STS (stage s): s8 [i][j-bytes], conflict-free row stores ----
    auto store_A = [&](int s) {
        const uint32_t dstBase = sb + (uint32_t)s * STAGE;
#pragma unroll
        for (int it = 0; it < 16; ++it) {
            const int idx = tid + it * 256;
            const int i = idx >> 5;
            const int j = (idx & 31) * 4;
            const uint4 v = areg[it];
            msum += v.x + v.y + v.z + v.w;
            asm volatile("st.shared.b32 [%0], %1;"
                :: "r"(dstBase + (uint32_t)i * PITCH + (uint32_t)j), "r"(pack01(v))
                : "memory");
        }
    };

    // ---- B (trig table) via cp.async: s8 [r=128 trig-rows][j-bytes] ----
    auto issue_B = [&](int g, int s) {
        const int j0 = (g & 63) * 128;
        const uint32_t dst = sb + (uint32_t)s * STAGE + TILE_SZ;
#pragma unroll
        for (int it = 0; it < 4; ++it) {
            const int idx = tid + it * 256;
            const int r = idx >> 3;
            const int gg = idx & 7;
            cp_async16(dst + (uint32_t)r * PITCH + (uint32_t)gg * 16,
                       (const char*)g_B8 + (size_t)r * NB + (size_t)j0 + (size_t)gg * 16);
        }
        CP_COMMIT();
    };

    // ---- compute one chunk (R4-validated s8 fragment mappings) ----
    auto compute = [&](int s) {
        const uint32_t aBase = sb + (uint32_t)s * STAGE
                             + (uint32_t)(wid * 16 + (lane & 15)) * PITCH + (uint32_t)(lane >> 4) * 16;
        const uint32_t bBase = sb + (uint32_t)s * STAGE + TILE_SZ
                             + (uint32_t)(lane >> 2) * PITCH + (uint32_t)(lane & 3) * 4;
#pragma unroll
        for (int ks = 0; ks < 4; ++ks) {
            uint32_t afr[4];
            LDSM_X4(afr, aBase + (uint32_t)ks * 32);
#pragma unroll
            for (int nj = 0; nj < 16; ++nj) {
                uint32_t b0, b1;
                const uint32_t ba = bBase + (uint32_t)(nj * 8) * PITCH + (uint32_t)ks * 32;
                asm volatile("ld.shared.b32 %0, [%1];" : "=r"(b0) : "r"(ba));
                asm volatile("ld.shared.b32 %0, [%1];" : "=r"(b1) : "r"(ba + 16));
                mma_s8(acc[nj], afr, b0, b1);
            }
        }
    };

    // ---- flush: fused ca/sa epilogue for i-tile it (R6-validated), reset acc ----
    float* cas    = reinterpret_cast<float*>(smem_raw);            // reuses stage region
    float* sas    = cas + 64 * CA_PITCH;
    float* real_s = reinterpret_cast<float*>(smem_raw + ACC_OFF);
    float* imag_s = real_s + 64;

    auto flush = [&](int itile) {
        const int i0 = itile * 128;
        if (tid < 64) { real_s[tid] = 0.0f; imag_s[tid] = 0.0f; }
#pragma unroll
        for (int it = 0; it < 8; ++it) {
            const int idx = tid + it * 256;   // 2048 float4 tasks
            const int r = idx >> 5;
            const int q = idx & 31;
            *reinterpret_cast<float4*>(&cas[r * CA_PITCH + q * 4]) =
                *reinterpret_cast<const float4*>(&g_caf[(size_t)r * NA + i0 + q * 4]);
            *reinterpret_cast<float4*>(&sas[r * CA_PITCH + q * 4]) =
                *reinterpret_cast<const float4*>(&g_saf[(size_t)r * NA + i0 + q * 4]);
        }
        __syncthreads();

        const float inv127 = 1.0f / 127.0f;
        const int il0 = wid * 16 + (lane >> 2);
#pragma unroll
        for (int nj2 = 0; nj2 < 8; ++nj2) {
#pragma unroll
            for (int h2 = 0; h2 < 2; ++h2) {
                const int b = nj2 * 8 + tc + h2;
                float rsum = 0.0f, isum = 0.0f;
#pragma unroll
                for (int hr = 0; hr < 2; ++hr) {
                    const int il = il0 + hr * 8;
                    const float XC = __int2float_rn(acc[nj2][hr * 2 + h2]);
                    const float XS = __int2float_rn(acc[nj2 + 8][hr * 2 + h2]);
                    const float ca = cas[b * CA_PITCH + il];
                    const float sa = sas[b * CA_PITCH + il];
                    rsum = fmaf(ca, XC, fmaf(sa, XS, rsum));
                    isum = fmaf(sa, XC, fmaf(-ca, XS, isum));
                }
                atomicAdd(&real_s[b], rsum * inv127);
                atomicAdd(&imag_s[b], isum * inv127);
            }
        }
        __syncthreads();
        if (tid < 64) {
            atomicAdd(&g_real[tid], real_s[tid]);
            atomicAdd(&g_imag[tid], imag_s[tid]);
        }
        __syncthreads();   // cas/sas (stage region) free before next run's writes
#pragma unroll
        for (int nj = 0; nj < 16; ++nj)
#pragma unroll
            for (int r = 0; r < 4; ++r) acc[nj][r] = 0;
    };

    // ---------------- persistent chunk runs (grouped by i-tile) ----------------
    int g = g0;
    while (g < g1) {
        const int itile = g >> 6;
        const int gend  = min(g1, (itile + 1) * NJC);
        const int nrun  = gend - g;

        load_A(g);
        issue_B(g, 0);
        store_A(0);
        CP_WAIT0();
        __syncthreads();

        for (int k = 0; k < nrun; ++k) {
            const int s = k & 1;
            if (k + 1 < nrun) {
                load_A(g + k + 1);          // LDGs in flight during compute
                issue_B(g + k + 1, s ^ 1);
            }
            compute(s);
            if (k + 1 < nrun) {
                store_A(s ^ 1);
                CP_WAIT0();
            }
            __syncthreads();
        }

        flush(itile);
        g = gend;
    }

    // ---- n_pairs reduce (each mask element converted exactly once globally) ----
#pragma unroll
    for (int o = 16; o; o >>= 1) msum += __shfl_down_sync(0xFFFFFFFFu, msum, o);
    if (lane == 0) atomicAdd(&g_npairs, msum);
}

// ---------------- final ----------------
__global__ void plv_final(float* __restrict__ out) {
    const int b = threadIdx.x;
    if (b < BATCH) {
        const float np = fmaxf((float)g_npairs, 1.0f);
        const float r = g_real[b], i = g_imag[b];
        out[b] = sqrtf(r * r + i * i) / np;
    }
}

// ---------------- launch ----------------
extern "C" void kernel_launch(void* const* d_in, const int* in_sizes, int n_in,
                              void* d_out, int out_size) {
    (void)in_sizes; (void)n_in; (void)out_size;
    const float* pa = (const float*)d_in[0];
    const float* pb = (const float*)d_in[1];
    const int* mask = (const int*)d_in[2];
    float* out      = (float*)d_out;

    cudaFuncSetAttribute(plv_main, cudaFuncAttributeMaxDynamicSharedMemorySize, SMEM_BYTES);

    plv_prep<<<(BATCH * NA + 255) / 256, 256>>>(pa, pb);
    plv_main<<<NCTA, NTHREADS, SMEM_BYTES>>>(mask);
    plv_final<<<1, 64>>>(out);
}